// round 1
// baseline (speedup 1.0000x reference)
#include <cuda_runtime.h>
#include <cstddef>

// ---------------- static device scratch (module-load allocated, no runtime alloc) ----
#define MAXN 100000
#define MAXE 1600000
#define HD   128

__device__ float g_h  [(size_t)MAXN * HD];   // GEMM output
__device__ float g_acc[(size_t)MAXN * HD];   // scatter accumulator
__device__ float g_y  [(size_t)MAXN * HD];   // post-BN activations
__device__ float g_norm[MAXE];
__device__ float g_dinv[MAXN];
__device__ int   g_deg [MAXN];

// ---------------- degree / norm precompute ----------------
__global__ void k_zero_deg(int* deg, int n) {
    int i = blockIdx.x * blockDim.x + threadIdx.x;
    if (i < n) deg[i] = 0;
}
__global__ void k_count_deg(const int* __restrict__ dst, int* deg, int e) {
    int i = blockIdx.x * blockDim.x + threadIdx.x;
    if (i < e) atomicAdd(&deg[dst[i]], 1);
}
__global__ void k_dinv(const int* __restrict__ deg, float* dinv, int n) {
    int i = blockIdx.x * blockDim.x + threadIdx.x;
    if (i < n) dinv[i] = rsqrtf((float)(deg[i] + 1));   // +1 self-loop; deg>=1 always
}
__global__ void k_norm(const int* __restrict__ src, const int* __restrict__ dst,
                       const float* __restrict__ dinv, float* norm, int e) {
    int i = blockIdx.x * blockDim.x + threadIdx.x;
    if (i < e) norm[i] = dinv[src[i]] * dinv[dst[i]];
}

// ---------------- fp32 GEMM: C[n,128] = A[n,128] @ B[128,128] ----------------
// 128x128 tile per CTA, 256 threads, 8x8 per thread, BK=8.
__global__ void k_gemm128(const float* __restrict__ A, const float* __restrict__ B,
                          float* __restrict__ C, int n) {
    __shared__ float As[8][128];
    __shared__ float Bs[8][128];
    const int t  = threadIdx.x;
    const int tx = t & 15;        // 0..15  -> output cols tx*8..+7
    const int ty = t >> 4;        // 0..15  -> output rows ty*8..+7
    const int r0 = blockIdx.x * 128;

    const int la_row = t >> 1;          // 0..127
    const int la_col = (t & 1) * 4;     // 0 or 4
    const int lb_row = t >> 5;          // 0..7
    const int lb_col = (t & 31) * 4;    // 0..124

    float acc[8][8];
    #pragma unroll
    for (int i = 0; i < 8; i++)
        #pragma unroll
        for (int j = 0; j < 8; j++) acc[i][j] = 0.f;

    for (int k0 = 0; k0 < 128; k0 += 8) {
        int grow = r0 + la_row;
        float4 av = make_float4(0.f, 0.f, 0.f, 0.f);
        if (grow < n) av = *(const float4*)(A + (size_t)grow * 128 + k0 + la_col);
        As[la_col + 0][la_row] = av.x;
        As[la_col + 1][la_row] = av.y;
        As[la_col + 2][la_row] = av.z;
        As[la_col + 3][la_row] = av.w;

        float4 bv = *(const float4*)(B + (size_t)(k0 + lb_row) * 128 + lb_col);
        *(float4*)(&Bs[lb_row][lb_col]) = bv;
        __syncthreads();

        #pragma unroll
        for (int k = 0; k < 8; k++) {
            float a[8], b[8];
            #pragma unroll
            for (int i = 0; i < 8; i++) a[i] = As[k][ty * 8 + i];
            #pragma unroll
            for (int j = 0; j < 8; j++) b[j] = Bs[k][tx * 8 + j];
            #pragma unroll
            for (int i = 0; i < 8; i++)
                #pragma unroll
                for (int j = 0; j < 8; j++)
                    acc[i][j] += a[i] * b[j];
        }
        __syncthreads();
    }

    #pragma unroll
    for (int i = 0; i < 8; i++) {
        int row = r0 + ty * 8 + i;
        if (row < n) {
            float4 v0 = make_float4(acc[i][0], acc[i][1], acc[i][2], acc[i][3]);
            float4 v1 = make_float4(acc[i][4], acc[i][5], acc[i][6], acc[i][7]);
            *(float4*)(C + (size_t)row * 128 + tx * 8)     = v0;
            *(float4*)(C + (size_t)row * 128 + tx * 8 + 4) = v1;
        }
    }
}

// ---------------- self-loop init: acc[i,:] = h[i,:] * dinv[i]^2 ----------------
__global__ void k_selfloop(const float* __restrict__ h, const float* __restrict__ dinv,
                           float* __restrict__ acc, int n) {
    int idx = blockIdx.x * blockDim.x + threadIdx.x;   // one float4 per thread
    if (idx >= n * 32) return;
    int row = idx >> 5;
    float d = dinv[row];
    float w = d * d;
    float4 v = *(const float4*)(h + (size_t)idx * 4);
    v.x *= w; v.y *= w; v.z *= w; v.w *= w;
    *(float4*)(acc + (size_t)idx * 4) = v;
}

// ---------------- edge scatter: acc[dst,:] += h[src,:] * norm[e] ----------------
// warp per edge: lane l handles features 4l..4l+3, coalesced 512B gather + v4 RED.
__global__ void k_scatter(const float* __restrict__ h, const int* __restrict__ src,
                          const int* __restrict__ dst, const float* __restrict__ norm,
                          float* __restrict__ acc, int e) {
    int gw   = (blockIdx.x * blockDim.x + threadIdx.x) >> 5;
    int lane = threadIdx.x & 31;
    int nw   = (gridDim.x * blockDim.x) >> 5;
    for (int i = gw; i < e; i += nw) {
        int   s = __ldg(src + i);
        int   d = __ldg(dst + i);
        float w = __ldg(norm + i);
        float4 v = __ldg((const float4*)(h + (size_t)s * 128) + lane);
        v.x *= w; v.y *= w; v.z *= w; v.w *= w;
        float* q = acc + (size_t)d * 128 + lane * 4;
        asm volatile("red.global.add.v4.f32 [%0], {%1,%2,%3,%4};"
                     :: "l"(q), "f"(v.x), "f"(v.y), "f"(v.z), "f"(v.w) : "memory");
    }
}

// ---------------- bias + relu + eval-BN ----------------
__global__ void k_bias_relu_bn(const float* __restrict__ acc, const float* __restrict__ b,
                               const float* __restrict__ g, const float* __restrict__ be,
                               const float* __restrict__ rm, const float* __restrict__ rv,
                               float* __restrict__ y, int n) {
    int idx = blockIdx.x * blockDim.x + threadIdx.x;   // one float4 per thread
    if (idx >= n * 32) return;
    int j = (idx & 31) * 4;
    float4 v = *(const float4*)(acc + (size_t)idx * 4);
    float o[4] = {v.x, v.y, v.z, v.w};
    #pragma unroll
    for (int c = 0; c < 4; c++) {
        int jj = j + c;
        float t = o[c] + __ldg(b + jj);
        t = fmaxf(t, 0.f);
        float scale = __ldg(g + jj) * rsqrtf(__ldg(rv + jj) + 1e-5f);
        o[c] = (t - __ldg(rm + jj)) * scale + __ldg(be + jj);
    }
    *(float4*)(y + (size_t)idx * 4) = make_float4(o[0], o[1], o[2], o[3]);
}

// ---------------- classifier: out[n,2] = y @ Wc + bc (warp per row) ----------------
__global__ void k_classifier(const float* __restrict__ y, const float* __restrict__ Wc,
                             const float* __restrict__ bc, float* __restrict__ out, int n) {
    int gw   = (blockIdx.x * blockDim.x + threadIdx.x) >> 5;
    int lane = threadIdx.x & 31;
    if (gw >= n) return;
    float4 v = *(const float4*)(y + (size_t)gw * 128 + lane * 4);
    int j = lane * 4;
    float a0 = v.x * __ldg(Wc + (j + 0) * 2)     + v.y * __ldg(Wc + (j + 1) * 2)
             + v.z * __ldg(Wc + (j + 2) * 2)     + v.w * __ldg(Wc + (j + 3) * 2);
    float a1 = v.x * __ldg(Wc + (j + 0) * 2 + 1) + v.y * __ldg(Wc + (j + 1) * 2 + 1)
             + v.z * __ldg(Wc + (j + 2) * 2 + 1) + v.w * __ldg(Wc + (j + 3) * 2 + 1);
    #pragma unroll
    for (int o = 16; o > 0; o >>= 1) {
        a0 += __shfl_xor_sync(0xFFFFFFFFu, a0, o);
        a1 += __shfl_xor_sync(0xFFFFFFFFu, a1, o);
    }
    if (lane == 0) {
        out[(size_t)gw * 2]     = a0 + __ldg(bc);
        out[(size_t)gw * 2 + 1] = a1 + __ldg(bc + 1);
    }
}

// ---------------- launcher ----------------
extern "C" void kernel_launch(void* const* d_in, const int* in_sizes, int n_in,
                              void* d_out, int out_size) {
    const float* x   = (const float*)d_in[0];
    const int*   ei  = (const int*)  d_in[1];   // int64 in source, but JAX x64 off -> int32
    const float* W1  = (const float*)d_in[2];
    const float* b1  = (const float*)d_in[3];
    const float* W2  = (const float*)d_in[4];
    const float* b2  = (const float*)d_in[5];
    const float* W3  = (const float*)d_in[6];
    const float* b3  = (const float*)d_in[7];
    const float* g1  = (const float*)d_in[8];
    const float* be1 = (const float*)d_in[9];
    const float* rm1 = (const float*)d_in[10];
    const float* rv1 = (const float*)d_in[11];
    const float* g2  = (const float*)d_in[12];
    const float* be2 = (const float*)d_in[13];
    const float* rm2 = (const float*)d_in[14];
    const float* rv2 = (const float*)d_in[15];
    const float* g3  = (const float*)d_in[16];
    const float* be3 = (const float*)d_in[17];
    const float* rm3 = (const float*)d_in[18];
    const float* rv3 = (const float*)d_in[19];
    const float* Wc  = (const float*)d_in[20];
    const float* bc  = (const float*)d_in[21];
    float* out = (float*)d_out;

    int n = in_sizes[0] / HD;      // nodes
    int e = in_sizes[1] / 2;       // edges (no self-loops)
    const int* src = ei;
    const int* dst = ei + e;

    float *ph, *pacc, *py, *pnorm, *pdinv;
    int* pdeg;
    cudaGetSymbolAddress((void**)&ph,    g_h);
    cudaGetSymbolAddress((void**)&pacc,  g_acc);
    cudaGetSymbolAddress((void**)&py,    g_y);
    cudaGetSymbolAddress((void**)&pnorm, g_norm);
    cudaGetSymbolAddress((void**)&pdinv, g_dinv);
    cudaGetSymbolAddress((void**)&pdeg,  g_deg);

    const int T = 256;
    int bn_n  = (n + T - 1) / T;
    int bn_e  = (e + T - 1) / T;
    int bn_el = (n * 32 + T - 1) / T;      // elementwise float4 grids
    int bn_gm = (n + 127) / 128;           // GEMM row blocks
    int bn_sc = 2048;                      // scatter grid-stride
    int bn_cl = (n * 32 + T - 1) / T;      // warp-per-row classifier

    // degree / norm precompute
    k_zero_deg <<<bn_n, T>>>(pdeg, n);
    k_count_deg<<<bn_e, T>>>(dst, pdeg, e);
    k_dinv     <<<bn_n, T>>>(pdeg, pdinv, n);
    k_norm     <<<bn_e, T>>>(src, dst, pdinv, pnorm, e);

    // layer 1
    k_gemm128  <<<bn_gm, T>>>(x, W1, ph, n);
    k_selfloop <<<bn_el, T>>>(ph, pdinv, pacc, n);
    k_scatter  <<<bn_sc, T>>>(ph, src, dst, pnorm, pacc, e);
    k_bias_relu_bn<<<bn_el, T>>>(pacc, b1, g1, be1, rm1, rv1, py, n);

    // layer 2
    k_gemm128  <<<bn_gm, T>>>(py, W2, ph, n);
    k_selfloop <<<bn_el, T>>>(ph, pdinv, pacc, n);
    k_scatter  <<<bn_sc, T>>>(ph, src, dst, pnorm, pacc, e);
    k_bias_relu_bn<<<bn_el, T>>>(pacc, b2, g2, be2, rm2, rv2, py, n);

    // layer 3
    k_gemm128  <<<bn_gm, T>>>(py, W3, ph, n);
    k_selfloop <<<bn_el, T>>>(ph, pdinv, pacc, n);
    k_scatter  <<<bn_sc, T>>>(ph, src, dst, pnorm, pacc, e);
    k_bias_relu_bn<<<bn_el, T>>>(pacc, b3, g3, be3, rm3, rv3, py, n);

    // classifier
    k_classifier<<<bn_cl, T>>>(py, Wc, bc, out, n);
}

// round 2
// speedup vs baseline: 1.7717x; 1.7717x over previous
#include <cuda_runtime.h>
#include <cstddef>

#define MAXN 100000
#define MAXE 1600000
#define HD   128

// ---------------- static device scratch ----------------
__device__ float g_h  [(size_t)MAXN * HD];   // hs = (in @ W) * dinv[row]
__device__ float g_y  [(size_t)MAXN * HD];   // post-BN activations
__device__ float g_dinv[MAXN];
__device__ int   g_cnt [MAXN];               // incoming-edge counts (no self loop)
__device__ int   g_rowptr[MAXN];             // exclusive scan of counts
__device__ int   g_cursor[MAXN];
__device__ int   g_csr [MAXE];               // src ids grouped by dst
__device__ int   g_bsum[256];

// ---------------- degree / CSR build ----------------
__global__ void k_zero(int* a, int n) {
    int i = blockIdx.x * blockDim.x + threadIdx.x;
    if (i < n) a[i] = 0;
}
__global__ void k_count(const int* __restrict__ dst, int* cnt, int e) {
    int i = blockIdx.x * blockDim.x + threadIdx.x;
    if (i < e) atomicAdd(&cnt[dst[i]], 1);
}
__global__ void k_dinv(const int* __restrict__ cnt, float* dinv, int n) {
    int i = blockIdx.x * blockDim.x + threadIdx.x;
    if (i < n) dinv[i] = rsqrtf((float)(cnt[i] + 1));   // +1 self-loop
}
// exclusive scan: per-block scan + block sums
__global__ void k_scan_block(const int* __restrict__ in, int* out, int* bsum, int n) {
    __shared__ int s[512];
    int i = blockIdx.x * 512 + threadIdx.x;
    int v = (i < n) ? in[i] : 0;
    s[threadIdx.x] = v;
    __syncthreads();
    #pragma unroll
    for (int o = 1; o < 512; o <<= 1) {
        int t = (threadIdx.x >= o) ? s[threadIdx.x - o] : 0;
        __syncthreads();
        s[threadIdx.x] += t;
        __syncthreads();
    }
    if (i < n) out[i] = s[threadIdx.x] - v;             // exclusive
    if (threadIdx.x == 511) bsum[blockIdx.x] = s[511];
}
__global__ void k_scan_sums(int* bsum, int nb) {        // single block, nb<=256
    __shared__ int s[256];
    int v = (threadIdx.x < nb) ? bsum[threadIdx.x] : 0;
    s[threadIdx.x] = v;
    __syncthreads();
    #pragma unroll
    for (int o = 1; o < 256; o <<= 1) {
        int t = (threadIdx.x >= o) ? s[threadIdx.x - o] : 0;
        __syncthreads();
        s[threadIdx.x] += t;
        __syncthreads();
    }
    if (threadIdx.x < nb) bsum[threadIdx.x] = s[threadIdx.x] - v;  // exclusive
}
__global__ void k_scan_add(int* out, int* cursor, const int* __restrict__ bsum, int n) {
    int i = blockIdx.x * 512 + threadIdx.x;
    if (i < n) {
        int v = out[i] + bsum[blockIdx.x];
        out[i] = v;
        cursor[i] = v;
    }
}
__global__ void k_fill(const int* __restrict__ src, const int* __restrict__ dst,
                       int* cursor, int* csr, int e) {
    int i = blockIdx.x * blockDim.x + threadIdx.x;
    if (i < e) {
        int p = atomicAdd(&cursor[dst[i]], 1);
        csr[p] = src[i];
    }
}

// ---------------- fp32 GEMM: hs[n,128] = (A[n,128] @ B[128,128]) * dinv[row] ----
__global__ void k_gemm128(const float* __restrict__ A, const float* __restrict__ B,
                          const float* __restrict__ dinv, float* __restrict__ C, int n) {
    __shared__ float As[8][128];
    __shared__ float Bs[8][128];
    const int t  = threadIdx.x;
    const int tx = t & 15;
    const int ty = t >> 4;
    const int r0 = blockIdx.x * 128;

    const int la_row = t >> 1;
    const int la_col = (t & 1) * 4;
    const int lb_row = t >> 5;
    const int lb_col = (t & 31) * 4;

    float acc[8][8];
    #pragma unroll
    for (int i = 0; i < 8; i++)
        #pragma unroll
        for (int j = 0; j < 8; j++) acc[i][j] = 0.f;

    for (int k0 = 0; k0 < 128; k0 += 8) {
        int grow = r0 + la_row;
        float4 av = make_float4(0.f, 0.f, 0.f, 0.f);
        if (grow < n) av = *(const float4*)(A + (size_t)grow * 128 + k0 + la_col);
        As[la_col + 0][la_row] = av.x;
        As[la_col + 1][la_row] = av.y;
        As[la_col + 2][la_row] = av.z;
        As[la_col + 3][la_row] = av.w;

        float4 bv = *(const float4*)(B + (size_t)(k0 + lb_row) * 128 + lb_col);
        *(float4*)(&Bs[lb_row][lb_col]) = bv;
        __syncthreads();

        #pragma unroll
        for (int k = 0; k < 8; k++) {
            float a[8], b[8];
            #pragma unroll
            for (int i = 0; i < 8; i++) a[i] = As[k][ty * 8 + i];
            #pragma unroll
            for (int j = 0; j < 8; j++) b[j] = Bs[k][tx * 8 + j];
            #pragma unroll
            for (int i = 0; i < 8; i++)
                #pragma unroll
                for (int j = 0; j < 8; j++)
                    acc[i][j] += a[i] * b[j];
        }
        __syncthreads();
    }

    #pragma unroll
    for (int i = 0; i < 8; i++) {
        int row = r0 + ty * 8 + i;
        if (row < n) {
            float w = __ldg(dinv + row);
            float4 v0 = make_float4(acc[i][0] * w, acc[i][1] * w, acc[i][2] * w, acc[i][3] * w);
            float4 v1 = make_float4(acc[i][4] * w, acc[i][5] * w, acc[i][6] * w, acc[i][7] * w);
            *(float4*)(C + (size_t)row * 128 + tx * 8)     = v0;
            *(float4*)(C + (size_t)row * 128 + tx * 8 + 4) = v1;
        }
    }
}

// ---------------- fused aggregate + bias + relu + BN ----------------
// warp per node: y[d,:] = BN(relu(dinv[d]*(hs[d,:] + sum_{s->d} hs[s,:]) + b))
__global__ void k_aggregate(const float* __restrict__ hs,
                            const int* __restrict__ rowptr, const int* __restrict__ cnt,
                            const float* __restrict__ dinv,
                            const float* __restrict__ b,  const float* __restrict__ g,
                            const float* __restrict__ be, const float* __restrict__ rm,
                            const float* __restrict__ rv, const int* __restrict__ csr,
                            float* __restrict__ y, int n) {
    int warp = (blockIdx.x * blockDim.x + threadIdx.x) >> 5;
    int lane = threadIdx.x & 31;
    int nw   = (gridDim.x * blockDim.x) >> 5;
    int j    = lane * 4;

    // per-channel constants (hoisted)
    float4 bb = __ldg((const float4*)(b  + j));
    float4 gg = __ldg((const float4*)(g  + j));
    float4 rr = __ldg((const float4*)(rv + j));
    float4 mm = __ldg((const float4*)(rm + j));
    float4 ee = __ldg((const float4*)(be + j));
    float sc0 = gg.x * rsqrtf(rr.x + 1e-5f), sh0 = ee.x - mm.x * sc0;
    float sc1 = gg.y * rsqrtf(rr.y + 1e-5f), sh1 = ee.y - mm.y * sc1;
    float sc2 = gg.z * rsqrtf(rr.z + 1e-5f), sh2 = ee.z - mm.z * sc2;
    float sc3 = gg.w * rsqrtf(rr.w + 1e-5f), sh3 = ee.w - mm.w * sc3;

    for (int d = warp; d < n; d += nw) {
        float4 a = __ldg((const float4*)(hs + (size_t)d * 128) + lane);  // self loop
        int beg = __ldg(rowptr + d);
        int c   = __ldg(cnt + d);
        int k = 0;
        for (; k + 4 <= c; k += 4) {
            int s0 = __ldg(csr + beg + k);
            int s1 = __ldg(csr + beg + k + 1);
            int s2 = __ldg(csr + beg + k + 2);
            int s3 = __ldg(csr + beg + k + 3);
            float4 v0 = __ldg((const float4*)(hs + (size_t)s0 * 128) + lane);
            float4 v1 = __ldg((const float4*)(hs + (size_t)s1 * 128) + lane);
            float4 v2 = __ldg((const float4*)(hs + (size_t)s2 * 128) + lane);
            float4 v3 = __ldg((const float4*)(hs + (size_t)s3 * 128) + lane);
            a.x += (v0.x + v1.x) + (v2.x + v3.x);
            a.y += (v0.y + v1.y) + (v2.y + v3.y);
            a.z += (v0.z + v1.z) + (v2.z + v3.z);
            a.w += (v0.w + v1.w) + (v2.w + v3.w);
        }
        for (; k < c; k++) {
            int s = __ldg(csr + beg + k);
            float4 v = __ldg((const float4*)(hs + (size_t)s * 128) + lane);
            a.x += v.x; a.y += v.y; a.z += v.z; a.w += v.w;
        }
        float w = __ldg(dinv + d);
        float t0 = fmaxf(a.x * w + bb.x, 0.f);
        float t1 = fmaxf(a.y * w + bb.y, 0.f);
        float t2 = fmaxf(a.z * w + bb.z, 0.f);
        float t3 = fmaxf(a.w * w + bb.w, 0.f);
        float4 o = make_float4(t0 * sc0 + sh0, t1 * sc1 + sh1,
                               t2 * sc2 + sh2, t3 * sc3 + sh3);
        *((float4*)(y + (size_t)d * 128) + lane) = o;
    }
}

// ---------------- classifier: out[n,2] = y @ Wc + bc (warp per row) ----------------
__global__ void k_classifier(const float* __restrict__ y, const float* __restrict__ Wc,
                             const float* __restrict__ bc, float* __restrict__ out, int n) {
    int gw   = (blockIdx.x * blockDim.x + threadIdx.x) >> 5;
    int lane = threadIdx.x & 31;
    if (gw >= n) return;
    float4 v = *(const float4*)(y + (size_t)gw * 128 + lane * 4);
    int j = lane * 4;
    float a0 = v.x * __ldg(Wc + (j + 0) * 2)     + v.y * __ldg(Wc + (j + 1) * 2)
             + v.z * __ldg(Wc + (j + 2) * 2)     + v.w * __ldg(Wc + (j + 3) * 2);
    float a1 = v.x * __ldg(Wc + (j + 0) * 2 + 1) + v.y * __ldg(Wc + (j + 1) * 2 + 1)
             + v.z * __ldg(Wc + (j + 2) * 2 + 1) + v.w * __ldg(Wc + (j + 3) * 2 + 1);
    #pragma unroll
    for (int o = 16; o > 0; o >>= 1) {
        a0 += __shfl_xor_sync(0xFFFFFFFFu, a0, o);
        a1 += __shfl_xor_sync(0xFFFFFFFFu, a1, o);
    }
    if (lane == 0) {
        out[(size_t)gw * 2]     = a0 + __ldg(bc);
        out[(size_t)gw * 2 + 1] = a1 + __ldg(bc + 1);
    }
}

// ---------------- launcher ----------------
extern "C" void kernel_launch(void* const* d_in, const int* in_sizes, int n_in,
                              void* d_out, int out_size) {
    const float* x   = (const float*)d_in[0];
    const int*   ei  = (const int*)  d_in[1];
    const float* W1  = (const float*)d_in[2];
    const float* b1  = (const float*)d_in[3];
    const float* W2  = (const float*)d_in[4];
    const float* b2  = (const float*)d_in[5];
    const float* W3  = (const float*)d_in[6];
    const float* b3  = (const float*)d_in[7];
    const float* g1  = (const float*)d_in[8];
    const float* be1 = (const float*)d_in[9];
    const float* rm1 = (const float*)d_in[10];
    const float* rv1 = (const float*)d_in[11];
    const float* g2  = (const float*)d_in[12];
    const float* be2 = (const float*)d_in[13];
    const float* rm2 = (const float*)d_in[14];
    const float* rv2 = (const float*)d_in[15];
    const float* g3  = (const float*)d_in[16];
    const float* be3 = (const float*)d_in[17];
    const float* rm3 = (const float*)d_in[18];
    const float* rv3 = (const float*)d_in[19];
    const float* Wc  = (const float*)d_in[20];
    const float* bc  = (const float*)d_in[21];
    float* out = (float*)d_out;

    int n = in_sizes[0] / HD;
    int e = in_sizes[1] / 2;
    const int* src = ei;
    const int* dst = ei + e;

    float *ph, *py, *pdinv;
    int *pcnt, *prow, *pcur, *pcsr, *pbsum;
    cudaGetSymbolAddress((void**)&ph,    g_h);
    cudaGetSymbolAddress((void**)&py,    g_y);
    cudaGetSymbolAddress((void**)&pdinv, g_dinv);
    cudaGetSymbolAddress((void**)&pcnt,  g_cnt);
    cudaGetSymbolAddress((void**)&prow,  g_rowptr);
    cudaGetSymbolAddress((void**)&pcur,  g_cursor);
    cudaGetSymbolAddress((void**)&pcsr,  g_csr);
    cudaGetSymbolAddress((void**)&pbsum, g_bsum);

    const int T = 256;
    int bn_n  = (n + T - 1) / T;
    int bn_e  = (e + T - 1) / T;
    int bn_gm = (n + 127) / 128;
    int nb_sc = (n + 511) / 512;          // scan blocks (<=256)
    int bn_ag = 2048;                      // aggregate grid-stride
    int bn_cl = (n * 32 + T - 1) / T;

    // CSR build + dinv
    k_zero      <<<bn_n, T>>>(pcnt, n);
    k_count     <<<bn_e, T>>>(dst, pcnt, e);
    k_dinv      <<<bn_n, T>>>(pcnt, pdinv, n);
    k_scan_block<<<nb_sc, 512>>>(pcnt, prow, pbsum, n);
    k_scan_sums <<<1, 256>>>(pbsum, nb_sc);
    k_scan_add  <<<nb_sc, 512>>>(prow, pcur, pbsum, n);
    k_fill      <<<bn_e, T>>>(src, dst, pcur, pcsr, e);

    // layer 1
    k_gemm128  <<<bn_gm, T>>>(x, W1, pdinv, ph, n);
    k_aggregate<<<bn_ag, T>>>(ph, prow, pcnt, pdinv, b1, g1, be1, rm1, rv1, pcsr, py, n);
    // layer 2
    k_gemm128  <<<bn_gm, T>>>(py, W2, pdinv, ph, n);
    k_aggregate<<<bn_ag, T>>>(ph, prow, pcnt, pdinv, b2, g2, be2, rm2, rv2, pcsr, py, n);
    // layer 3
    k_gemm128  <<<bn_gm, T>>>(py, W3, pdinv, ph, n);
    k_aggregate<<<bn_ag, T>>>(ph, prow, pcnt, pdinv, b3, g3, be3, rm3, rv3, pcsr, py, n);

    // classifier
    k_classifier<<<bn_cl, T>>>(py, Wc, bc, out, n);
}

// round 4
// speedup vs baseline: 2.5122x; 1.4179x over previous
#include <cuda_runtime.h>
#include <cuda_bf16.h>
#include <cstdint>
#include <cstddef>

#define MAXN 100000
#define MAXE 1600000
#define HD   128

// ---------------- static device scratch ----------------
__device__ float    g_h  [(size_t)MAXN * HD];
__device__ float    g_y  [(size_t)MAXN * HD];
__device__ float    g_dinv[MAXN];
__device__ int      g_cnt [MAXN];
__device__ int      g_rowptr[MAXN];
__device__ int      g_cursor[MAXN];
__device__ int      g_csr [MAXE];
__device__ int      g_bsum[256];
__device__ uint32_t g_whi[8192];     // W split hi, packed bf16x2, layout [n][k2]
__device__ uint32_t g_wlo[8192];

// ---------------- degree / CSR build ----------------
__global__ void k_zero(int* a, int n) {
    int i = blockIdx.x * blockDim.x + threadIdx.x;
    if (i < n) a[i] = 0;
}
__global__ void k_count(const int* __restrict__ dst, int* cnt, int e) {
    int i = blockIdx.x * blockDim.x + threadIdx.x;
    if (i < e) atomicAdd(&cnt[dst[i]], 1);
}
__global__ void k_dinv(const int* __restrict__ cnt, float* dinv, int n) {
    int i = blockIdx.x * blockDim.x + threadIdx.x;
    if (i < n) dinv[i] = rsqrtf((float)(cnt[i] + 1));
}
__global__ void k_scan_block(const int* __restrict__ in, int* out, int* bsum, int n) {
    __shared__ int s[512];
    int i = blockIdx.x * 512 + threadIdx.x;
    int v = (i < n) ? in[i] : 0;
    s[threadIdx.x] = v;
    __syncthreads();
    #pragma unroll
    for (int o = 1; o < 512; o <<= 1) {
        int t = (threadIdx.x >= o) ? s[threadIdx.x - o] : 0;
        __syncthreads();
        s[threadIdx.x] += t;
        __syncthreads();
    }
    if (i < n) out[i] = s[threadIdx.x] - v;
    if (threadIdx.x == 511) bsum[blockIdx.x] = s[511];
}
__global__ void k_scan_sums(int* bsum, int nb) {
    __shared__ int s[256];
    int v = (threadIdx.x < nb) ? bsum[threadIdx.x] : 0;
    s[threadIdx.x] = v;
    __syncthreads();
    #pragma unroll
    for (int o = 1; o < 256; o <<= 1) {
        int t = (threadIdx.x >= o) ? s[threadIdx.x - o] : 0;
        __syncthreads();
        s[threadIdx.x] += t;
        __syncthreads();
    }
    if (threadIdx.x < nb) bsum[threadIdx.x] = s[threadIdx.x] - v;
}
__global__ void k_scan_add(int* out, int* cursor, const int* __restrict__ bsum, int n) {
    int i = blockIdx.x * 512 + threadIdx.x;
    if (i < n) {
        int v = out[i] + bsum[blockIdx.x];
        out[i] = v;
        cursor[i] = v;
    }
}
__global__ void k_fill(const int* __restrict__ src, const int* __restrict__ dst,
                       int* cursor, int* csr, int e) {
    int i = blockIdx.x * blockDim.x + threadIdx.x;
    if (i < e) {
        int p = atomicAdd(&cursor[dst[i]], 1);
        csr[p] = src[i];
    }
}

// ---------------- W split: W[k][n] fp32 -> packed bf16x2 hi/lo, [n][k2] ----------------
__global__ void k_wsplit(const float* __restrict__ W, uint32_t* whi, uint32_t* wlo) {
    int i = blockIdx.x * blockDim.x + threadIdx.x;   // 8192 outputs
    if (i >= 8192) return;
    int nn = i >> 6;
    int k2 = i & 63;
    float f0 = __ldg(W + (size_t)(2 * k2)     * 128 + nn);
    float f1 = __ldg(W + (size_t)(2 * k2 + 1) * 128 + nn);
    __nv_bfloat16 h0 = __float2bfloat16_rn(f0), h1 = __float2bfloat16_rn(f1);
    __nv_bfloat16 l0 = __float2bfloat16_rn(f0 - __bfloat162float(h0));
    __nv_bfloat16 l1 = __float2bfloat16_rn(f1 - __bfloat162float(h1));
    whi[i] = ((uint32_t)__bfloat16_as_ushort(h1) << 16) | (uint32_t)__bfloat16_as_ushort(h0);
    wlo[i] = ((uint32_t)__bfloat16_as_ushort(l1) << 16) | (uint32_t)__bfloat16_as_ushort(l0);
}

// ---------------- bf16-split HMMA GEMM: C = (A @ W) * dinv[row] ----------------
__device__ __forceinline__ void mma16816(float* d, const uint32_t* a, const uint32_t* b) {
    asm volatile("mma.sync.aligned.m16n8k16.row.col.f32.bf16.bf16.f32 "
        "{%0,%1,%2,%3}, {%4,%5,%6,%7}, {%8,%9}, {%0,%1,%2,%3};"
        : "+f"(d[0]), "+f"(d[1]), "+f"(d[2]), "+f"(d[3])
        : "r"(a[0]), "r"(a[1]), "r"(a[2]), "r"(a[3]), "r"(b[0]), "r"(b[1]));
}

// smem: 4 buffers of [128 rows][36 u32] (32 data + 4 pad; bank = (4g+t)%32 conflict-free)
#define ROWSTR 36
#define BUFU32 (128 * ROWSTR)          // 4608
#define GEMM_SMEM (4 * BUFU32 * 4)     // 73728 bytes

__global__ void __launch_bounds__(256, 2)
k_gemm_mma(const float* __restrict__ A, const uint32_t* __restrict__ Bhi,
           const uint32_t* __restrict__ Blo, const float* __restrict__ dinv,
           float* __restrict__ C, int n) {
    extern __shared__ uint32_t sm[];
    uint32_t* As_hi = sm;
    uint32_t* As_lo = sm + BUFU32;
    uint32_t* Bs_hi = sm + 2 * BUFU32;
    uint32_t* Bs_lo = sm + 3 * BUFU32;

    const int tid  = threadIdx.x;
    const int wid  = tid >> 5;
    const int lane = tid & 31;
    const int g    = lane >> 2;
    const int t    = lane & 3;
    const int wm   = wid & 3;          // warp M index: rows wm*32..+31
    const int wn   = wid >> 2;         // warp N index: cols wn*64..+63
    const int r0   = blockIdx.x * 128;

    float acc[2][8][4];
    #pragma unroll
    for (int a = 0; a < 2; a++)
        #pragma unroll
        for (int b = 0; b < 8; b++)
            #pragma unroll
            for (int c = 0; c < 4; c++) acc[a][b][c] = 0.f;

    #pragma unroll
    for (int ch = 0; ch < 2; ch++) {   // K chunks of 64
        __syncthreads();
        // --- A chunk: fp32 -> bf16 hi/lo packed u32 [row][k2] ---
        #pragma unroll
        for (int it = 0; it < 8; it++) {
            int f   = tid + it * 256;          // float4 id, 2048 total
            int row = f >> 4;
            int q   = f & 15;
            int gr  = r0 + row;
            float4 v = make_float4(0.f, 0.f, 0.f, 0.f);
            if (gr < n) v = *(const float4*)(A + (size_t)gr * 128 + ch * 64 + q * 4);
            __nv_bfloat16 hx = __float2bfloat16_rn(v.x), hy = __float2bfloat16_rn(v.y);
            __nv_bfloat16 hz = __float2bfloat16_rn(v.z), hw = __float2bfloat16_rn(v.w);
            __nv_bfloat16 lx = __float2bfloat16_rn(v.x - __bfloat162float(hx));
            __nv_bfloat16 ly = __float2bfloat16_rn(v.y - __bfloat162float(hy));
            __nv_bfloat16 lz = __float2bfloat16_rn(v.z - __bfloat162float(hz));
            __nv_bfloat16 lw = __float2bfloat16_rn(v.w - __bfloat162float(hw));
            int p = row * ROWSTR + q * 2;
            As_hi[p]     = ((uint32_t)__bfloat16_as_ushort(hy) << 16) | __bfloat16_as_ushort(hx);
            As_hi[p + 1] = ((uint32_t)__bfloat16_as_ushort(hw) << 16) | __bfloat16_as_ushort(hz);
            As_lo[p]     = ((uint32_t)__bfloat16_as_ushort(ly) << 16) | __bfloat16_as_ushort(lx);
            As_lo[p + 1] = ((uint32_t)__bfloat16_as_ushort(lw) << 16) | __bfloat16_as_ushort(lz);
        }
        // --- B chunk: copy pre-split [n][k2] ---
        #pragma unroll
        for (int it = 0; it < 16; it++) {
            int i  = tid + it * 256;           // 4096 u32 per buffer
            int nn = i >> 5;
            int k2 = i & 31;
            Bs_hi[nn * ROWSTR + k2] = __ldg(Bhi + nn * 64 + ch * 32 + k2);
            Bs_lo[nn * ROWSTR + k2] = __ldg(Blo + nn * 64 + ch * 32 + k2);
        }
        __syncthreads();

        #pragma unroll
        for (int ks = 0; ks < 4; ks++) {       // k-steps of 16 within chunk
            uint32_t ah[2][4], al[2][4];
            #pragma unroll
            for (int mt = 0; mt < 2; mt++) {
                int rb = wm * 32 + mt * 16;
                int p0 = (rb + g)     * ROWSTR + ks * 8 + t;
                int p8 = (rb + g + 8) * ROWSTR + ks * 8 + t;
                ah[mt][0] = As_hi[p0]; ah[mt][1] = As_hi[p8];
                ah[mt][2] = As_hi[p0 + 4]; ah[mt][3] = As_hi[p8 + 4];
                al[mt][0] = As_lo[p0]; al[mt][1] = As_lo[p8];
                al[mt][2] = As_lo[p0 + 4]; al[mt][3] = As_lo[p8 + 4];
            }
            #pragma unroll
            for (int nt = 0; nt < 8; nt++) {
                int nb = (wn * 64 + nt * 8 + g) * ROWSTR + ks * 8 + t;
                uint32_t bh[2] = {Bs_hi[nb], Bs_hi[nb + 4]};
                uint32_t bl[2] = {Bs_lo[nb], Bs_lo[nb + 4]};
                #pragma unroll
                for (int mt = 0; mt < 2; mt++) {
                    mma16816(acc[mt][nt], ah[mt], bh);   // hi*hi
                    mma16816(acc[mt][nt], ah[mt], bl);   // hi*lo
                    mma16816(acc[mt][nt], al[mt], bh);   // lo*hi
                }
            }
        }
    }

    // --- epilogue: scale by dinv[row], direct coalesced-per-quad float2 stores ---
    #pragma unroll
    for (int mt = 0; mt < 2; mt++) {
        int row0 = r0 + wm * 32 + mt * 16 + g;
        int row1 = row0 + 8;
        float dv0 = (row0 < n) ? __ldg(dinv + row0) : 0.f;
        float dv1 = (row1 < n) ? __ldg(dinv + row1) : 0.f;
        #pragma unroll
        for (int nt = 0; nt < 8; nt++) {
            int col = wn * 64 + nt * 8 + t * 2;
            if (row0 < n) {
                float2 v = make_float2(acc[mt][nt][0] * dv0, acc[mt][nt][1] * dv0);
                *(float2*)(C + (size_t)row0 * 128 + col) = v;
            }
            if (row1 < n) {
                float2 v = make_float2(acc[mt][nt][2] * dv1, acc[mt][nt][3] * dv1);
                *(float2*)(C + (size_t)row1 * 128 + col) = v;
            }
        }
    }
}

// ---------------- fused aggregate + bias + relu + BN ----------------
__global__ void k_aggregate(const float* __restrict__ hs,
                            const int* __restrict__ rowptr, const int* __restrict__ cnt,
                            const float* __restrict__ dinv,
                            const float* __restrict__ b,  const float* __restrict__ g,
                            const float* __restrict__ be, const float* __restrict__ rm,
                            const float* __restrict__ rv, const int* __restrict__ csr,
                            float* __restrict__ y, int n) {
    int warp = (blockIdx.x * blockDim.x + threadIdx.x) >> 5;
    int lane = threadIdx.x & 31;
    int nw   = (gridDim.x * blockDim.x) >> 5;
    int j    = lane * 4;

    float4 bb = __ldg((const float4*)(b  + j));
    float4 gg = __ldg((const float4*)(g  + j));
    float4 rr = __ldg((const float4*)(rv + j));
    float4 mm = __ldg((const float4*)(rm + j));
    float4 ee = __ldg((const float4*)(be + j));
    float sc0 = gg.x * rsqrtf(rr.x + 1e-5f), sh0 = ee.x - mm.x * sc0;
    float sc1 = gg.y * rsqrtf(rr.y + 1e-5f), sh1 = ee.y - mm.y * sc1;
    float sc2 = gg.z * rsqrtf(rr.z + 1e-5f), sh2 = ee.z - mm.z * sc2;
    float sc3 = gg.w * rsqrtf(rr.w + 1e-5f), sh3 = ee.w - mm.w * sc3;

    for (int d = warp; d < n; d += nw) {
        float4 a = __ldg((const float4*)(hs + (size_t)d * 128) + lane);
        int beg = __ldg(rowptr + d);
        int c   = __ldg(cnt + d);
        int k = 0;
        for (; k + 4 <= c; k += 4) {
            int s0 = __ldg(csr + beg + k);
            int s1 = __ldg(csr + beg + k + 1);
            int s2 = __ldg(csr + beg + k + 2);
            int s3 = __ldg(csr + beg + k + 3);
            float4 v0 = __ldg((const float4*)(hs + (size_t)s0 * 128) + lane);
            float4 v1 = __ldg((const float4*)(hs + (size_t)s1 * 128) + lane);
            float4 v2 = __ldg((const float4*)(hs + (size_t)s2 * 128) + lane);
            float4 v3 = __ldg((const float4*)(hs + (size_t)s3 * 128) + lane);
            a.x += (v0.x + v1.x) + (v2.x + v3.x);
            a.y += (v0.y + v1.y) + (v2.y + v3.y);
            a.z += (v0.z + v1.z) + (v2.z + v3.z);
            a.w += (v0.w + v1.w) + (v2.w + v3.w);
        }
        for (; k < c; k++) {
            int s = __ldg(csr + beg + k);
            float4 v = __ldg((const float4*)(hs + (size_t)s * 128) + lane);
            a.x += v.x; a.y += v.y; a.z += v.z; a.w += v.w;
        }
        float w = __ldg(dinv + d);
        float t0 = fmaxf(a.x * w + bb.x, 0.f);
        float t1 = fmaxf(a.y * w + bb.y, 0.f);
        float t2 = fmaxf(a.z * w + bb.z, 0.f);
        float t3 = fmaxf(a.w * w + bb.w, 0.f);
        float4 o = make_float4(t0 * sc0 + sh0, t1 * sc1 + sh1,
                               t2 * sc2 + sh2, t3 * sc3 + sh3);
        *((float4*)(y + (size_t)d * 128) + lane) = o;
    }
}

// ---------------- classifier ----------------
__global__ void k_classifier(const float* __restrict__ y, const float* __restrict__ Wc,
                             const float* __restrict__ bc, float* __restrict__ out, int n) {
    int gw   = (blockIdx.x * blockDim.x + threadIdx.x) >> 5;
    int lane = threadIdx.x & 31;
    if (gw >= n) return;
    float4 v = *(const float4*)(y + (size_t)gw * 128 + lane * 4);
    int j = lane * 4;
    float a0 = v.x * __ldg(Wc + (j + 0) * 2)     + v.y * __ldg(Wc + (j + 1) * 2)
             + v.z * __ldg(Wc + (j + 2) * 2)     + v.w * __ldg(Wc + (j + 3) * 2);
    float a1 = v.x * __ldg(Wc + (j + 0) * 2 + 1) + v.y * __ldg(Wc + (j + 1) * 2 + 1)
             + v.z * __ldg(Wc + (j + 2) * 2 + 1) + v.w * __ldg(Wc + (j + 3) * 2 + 1);
    #pragma unroll
    for (int o = 16; o > 0; o >>= 1) {
        a0 += __shfl_xor_sync(0xFFFFFFFFu, a0, o);
        a1 += __shfl_xor_sync(0xFFFFFFFFu, a1, o);
    }
    if (lane == 0) {
        out[(size_t)gw * 2]     = a0 + __ldg(bc);
        out[(size_t)gw * 2 + 1] = a1 + __ldg(bc + 1);
    }
}

// ---------------- launcher ----------------
extern "C" void kernel_launch(void* const* d_in, const int* in_sizes, int n_in,
                              void* d_out, int out_size) {
    const float* x   = (const float*)d_in[0];
    const int*   ei  = (const int*)  d_in[1];
    const float* W1  = (const float*)d_in[2];
    const float* b1  = (const float*)d_in[3];
    const float* W2  = (const float*)d_in[4];
    const float* b2  = (const float*)d_in[5];
    const float* W3  = (const float*)d_in[6];
    const float* b3  = (const float*)d_in[7];
    const float* g1  = (const float*)d_in[8];
    const float* be1 = (const float*)d_in[9];
    const float* rm1 = (const float*)d_in[10];
    const float* rv1 = (const float*)d_in[11];
    const float* g2  = (const float*)d_in[12];
    const float* be2 = (const float*)d_in[13];
    const float* rm2 = (const float*)d_in[14];
    const float* rv2 = (const float*)d_in[15];
    const float* g3  = (const float*)d_in[16];
    const float* be3 = (const float*)d_in[17];
    const float* rm3 = (const float*)d_in[18];
    const float* rv3 = (const float*)d_in[19];
    const float* Wc  = (const float*)d_in[20];
    const float* bc  = (const float*)d_in[21];
    float* out = (float*)d_out;

    int n = in_sizes[0] / HD;
    int e = in_sizes[1] / 2;
    const int* src = ei;
    const int* dst = ei + e;

    float *ph, *py, *pdinv;
    int *pcnt, *prow, *pcur, *pcsr, *pbsum;
    uint32_t *pwhi, *pwlo;
    cudaGetSymbolAddress((void**)&ph,    g_h);
    cudaGetSymbolAddress((void**)&py,    g_y);
    cudaGetSymbolAddress((void**)&pdinv, g_dinv);
    cudaGetSymbolAddress((void**)&pcnt,  g_cnt);
    cudaGetSymbolAddress((void**)&prow,  g_rowptr);
    cudaGetSymbolAddress((void**)&pcur,  g_cursor);
    cudaGetSymbolAddress((void**)&pcsr,  g_csr);
    cudaGetSymbolAddress((void**)&pbsum, g_bsum);
    cudaGetSymbolAddress((void**)&pwhi,  g_whi);
    cudaGetSymbolAddress((void**)&pwlo,  g_wlo);

    cudaFuncSetAttribute(k_gemm_mma, cudaFuncAttributeMaxDynamicSharedMemorySize, GEMM_SMEM);

    const int T = 256;
    int bn_n  = (n + T - 1) / T;
    int bn_e  = (e + T - 1) / T;
    int bn_gm = (n + 127) / 128;
    int nb_sc = (n + 511) / 512;
    int bn_ag = 2048;
    int bn_cl = (n * 32 + T - 1) / T;

    // CSR build + dinv
    k_zero      <<<bn_n, T>>>(pcnt, n);
    k_count     <<<bn_e, T>>>(dst, pcnt, e);
    k_dinv      <<<bn_n, T>>>(pcnt, pdinv, n);
    k_scan_block<<<nb_sc, 512>>>(pcnt, prow, pbsum, n);
    k_scan_sums <<<1, 256>>>(pbsum, nb_sc);
    k_scan_add  <<<nb_sc, 512>>>(prow, pcur, pbsum, n);
    k_fill      <<<bn_e, T>>>(src, dst, pcur, pcsr, e);

    // layer 1
    k_wsplit   <<<32, 256>>>(W1, pwhi, pwlo);
    k_gemm_mma <<<bn_gm, 256, GEMM_SMEM>>>(x, pwhi, pwlo, pdinv, ph, n);
    k_aggregate<<<bn_ag, T>>>(ph, prow, pcnt, pdinv, b1, g1, be1, rm1, rv1, pcsr, py, n);
    // layer 2
    k_wsplit   <<<32, 256>>>(W2, pwhi, pwlo);
    k_gemm_mma <<<bn_gm, 256, GEMM_SMEM>>>(py, pwhi, pwlo, pdinv, ph, n);
    k_aggregate<<<bn_ag, T>>>(ph, prow, pcnt, pdinv, b2, g2, be2, rm2, rv2, pcsr, py, n);
    // layer 3
    k_wsplit   <<<32, 256>>>(W3, pwhi, pwlo);
    k_gemm_mma <<<bn_gm, 256, GEMM_SMEM>>>(py, pwhi, pwlo, pdinv, ph, n);
    k_aggregate<<<bn_ag, T>>>(ph, prow, pcnt, pdinv, b3, g3, be3, rm3, rv3, pcsr, py, n);

    // classifier
    k_classifier<<<bn_cl, T>>>(py, Wc, bc, out, n);
}